// round 1
// baseline (speedup 1.0000x reference)
#include <cuda_runtime.h>
#include <math.h>

#define NB      2
#define LQ      12240
#define DIM     256
#define HEADS   8
#define LEVELS  4
#define POINTS  4
#define HD      32
#define MROWS   (NB * LQ)   // 24480

// Scratch (allocation-free requirement -> __device__ globals)
__device__ float g_value  [MROWS * DIM];
__device__ float g_off    [MROWS * DIM];          // 8*4*4*2 = 256 cols
__device__ float g_attn   [MROWS * HEADS * 16];   // 128 cols
__device__ float g_attout [MROWS * DIM];
__device__ float g_out2   [MROWS * DIM];

// ---------------------------------------------------------------------------
// GEMM: C[M,N] = A[M,K] * B[K,N] + bias[N]   (all row-major, fp32)
// BM=128, BN=64, BK=16, thread tile 8x4, 256 threads
// ---------------------------------------------------------------------------
#define BM 128
#define BN 64
#define BK 16
#define TM 8
#define TN 4

__global__ __launch_bounds__(256) void gemm_bias_kernel(
    const float* __restrict__ A, const float* __restrict__ B,
    const float* __restrict__ bias, float* __restrict__ C,
    int M, int N, int K)
{
    __shared__ float As[BK][BM + 4];   // transposed A tile, padded (stride 132 -> 16B aligned rows)
    __shared__ float Bs[BK][BN + 4];   // stride 68 -> 16B aligned rows

    const int tid = threadIdx.x;
    const int tx = tid & 15;          // 0..15 col group
    const int ty = tid >> 4;          // 0..15 row group
    const int bm = blockIdx.y * BM;
    const int bn = blockIdx.x * BN;

    // A load mapping: each thread loads 8 elems (2 float4), same row
    const int a_row = tid >> 1;              // 0..127
    const int a_col = (tid & 1) * 8;         // 0 or 8
    // B load mapping: each thread loads 1 float4
    const int b_row = tid >> 4;              // 0..15
    const int b_col = (tid & 15) * 4;        // 0..60

    float acc[TM][TN];
#pragma unroll
    for (int i = 0; i < TM; i++)
#pragma unroll
        for (int j = 0; j < TN; j++) acc[i][j] = 0.f;

    const bool a_valid = (bm + a_row) < M;

    for (int kk = 0; kk < K; kk += BK) {
        float4 va0 = make_float4(0.f, 0.f, 0.f, 0.f);
        float4 va1 = va0;
        if (a_valid) {
            const float* ap = &A[(size_t)(bm + a_row) * K + kk + a_col];
            va0 = *(const float4*)(ap);
            va1 = *(const float4*)(ap + 4);
        }
        // store transposed
        As[a_col + 0][a_row] = va0.x;
        As[a_col + 1][a_row] = va0.y;
        As[a_col + 2][a_row] = va0.z;
        As[a_col + 3][a_row] = va0.w;
        As[a_col + 4][a_row] = va1.x;
        As[a_col + 5][a_row] = va1.y;
        As[a_col + 6][a_row] = va1.z;
        As[a_col + 7][a_row] = va1.w;

        float4 vb = *(const float4*)&B[(size_t)(kk + b_row) * N + bn + b_col];
        *(float4*)&Bs[b_row][b_col] = vb;

        __syncthreads();

#pragma unroll
        for (int k = 0; k < BK; k++) {
            float4 a0 = *(const float4*)&As[k][ty * TM];
            float4 a1 = *(const float4*)&As[k][ty * TM + 4];
            float4 b  = *(const float4*)&Bs[k][tx * TN];
            float ar[TM] = {a0.x, a0.y, a0.z, a0.w, a1.x, a1.y, a1.z, a1.w};
            float br[TN] = {b.x, b.y, b.z, b.w};
#pragma unroll
            for (int i = 0; i < TM; i++)
#pragma unroll
                for (int j = 0; j < TN; j++)
                    acc[i][j] = fmaf(ar[i], br[j], acc[i][j]);
        }
        __syncthreads();
    }

    float4 bv = *(const float4*)&bias[bn + tx * TN];
    float brg[TN] = {bv.x, bv.y, bv.z, bv.w};
#pragma unroll
    for (int i = 0; i < TM; i++) {
        int row = bm + ty * TM + i;
        if (row < M) {
            float4 o;
            o.x = acc[i][0] + brg[0];
            o.y = acc[i][1] + brg[1];
            o.z = acc[i][2] + brg[2];
            o.w = acc[i][3] + brg[3];
            *(float4*)&C[(size_t)row * N + bn + tx * TN] = o;
        }
    }
}

// ---------------------------------------------------------------------------
// Deformable sampling: 1 block per query, warp == head, lane == channel
// ---------------------------------------------------------------------------
__global__ __launch_bounds__(256) void sample_kernel(
    const float* __restrict__ value,
    const float* __restrict__ off,
    const float* __restrict__ logits,
    const float* __restrict__ ref,
    float* __restrict__ out)
{
    const int qg = blockIdx.x;            // 0..MROWS-1
    const int n  = qg / LQ;
    const int h    = threadIdx.x >> 5;
    const int lane = threadIdx.x & 31;

    // softmax over 16 attention logits for this (q, head) — redundant per lane (broadcast loads)
    const float* lg = logits + (size_t)qg * (HEADS * 16) + h * 16;
    float e[16];
    float mx = -1e30f;
#pragma unroll
    for (int i = 0; i < 16; i++) { e[i] = lg[i]; mx = fmaxf(mx, e[i]); }
    float s = 0.f;
#pragma unroll
    for (int i = 0; i < 16; i++) { e[i] = __expf(e[i] - mx); s += e[i]; }
    const float invs = 1.0f / s;

    const float* rp = ref + (size_t)qg * (LEVELS * 2);
    const float* ob = off + (size_t)qg * DIM + h * (LEVELS * POINTS * 2);

    const int Ws[LEVELS] = {96, 48, 24, 12};
    const int Hs[LEVELS] = {96, 48, 24, 12};
    const int S0[LEVELS] = {0, 9216, 11520, 12096};

    float acc = 0.f;
#pragma unroll
    for (int l = 0; l < LEVELS; l++) {
        const int Wl = Ws[l], Hl = Hs[l];
        const float rx = rp[l * 2 + 0] * (float)Wl;
        const float ry = rp[l * 2 + 1] * (float)Hl;
        const float* vbase = value + ((size_t)(n * LQ + S0[l])) * DIM + h * HD + lane;
#pragma unroll
        for (int p = 0; p < POINTS; p++) {
            const float x = rx + ob[(l * POINTS + p) * 2 + 0] - 0.5f;
            const float y = ry + ob[(l * POINTS + p) * 2 + 1] - 0.5f;
            const float x0f = floorf(x);
            const float y0f = floorf(y);
            const int x0 = (int)x0f;
            const int y0 = (int)y0f;
            const float fx = x - x0f;
            const float fy = y - y0f;
            const float aw = e[l * POINTS + p] * invs;
            const float w00 = (1.f - fx) * (1.f - fy) * aw;
            const float w01 = fx * (1.f - fy) * aw;
            const float w10 = (1.f - fx) * fy * aw;
            const float w11 = fx * fy * aw;
            const bool vx0 = (x0 >= 0) && (x0 < Wl);
            const bool vx1 = (x0 + 1 >= 0) && (x0 + 1 < Wl);
            const bool vy0 = (y0 >= 0) && (y0 < Hl);
            const bool vy1 = (y0 + 1 >= 0) && (y0 + 1 < Hl);
            if (vy0 && vx0) acc = fmaf(w00, vbase[(size_t)(y0 * Wl + x0) * DIM], acc);
            if (vy0 && vx1) acc = fmaf(w01, vbase[(size_t)(y0 * Wl + x0 + 1) * DIM], acc);
            if (vy1 && vx0) acc = fmaf(w10, vbase[(size_t)((y0 + 1) * Wl + x0) * DIM], acc);
            if (vy1 && vx1) acc = fmaf(w11, vbase[(size_t)((y0 + 1) * Wl + x0 + 1) * DIM], acc);
        }
    }
    out[(size_t)qg * DIM + h * HD + lane] = acc;
}

// ---------------------------------------------------------------------------
// Residual + LayerNorm: 1 block per row (256 threads == DIM)
// ---------------------------------------------------------------------------
__global__ __launch_bounds__(256) void ln_kernel(
    const float* __restrict__ src, const float* __restrict__ y,
    const float* __restrict__ gamma, const float* __restrict__ beta,
    float* __restrict__ out)
{
    const int row = blockIdx.x;
    const int t = threadIdx.x;
    const size_t idx = (size_t)row * DIM + t;
    const float x = src[idx] + y[idx];

    float s = x, s2 = x * x;
#pragma unroll
    for (int o = 16; o > 0; o >>= 1) {
        s  += __shfl_down_sync(0xffffffffu, s, o);
        s2 += __shfl_down_sync(0xffffffffu, s2, o);
    }
    __shared__ float ss[8], ss2[8];
    const int w = t >> 5;
    if ((t & 31) == 0) { ss[w] = s; ss2[w] = s2; }
    __syncthreads();
    float sum = 0.f, sum2 = 0.f;
#pragma unroll
    for (int i = 0; i < 8; i++) { sum += ss[i]; sum2 += ss2[i]; }

    const float mu  = sum * (1.0f / DIM);
    const float var = sum2 * (1.0f / DIM) - mu * mu;
    const float r = rsqrtf(var + 1e-5f);
    out[idx] = (x - mu) * r * gamma[t] + beta[t];
}

// ---------------------------------------------------------------------------
extern "C" void kernel_launch(void* const* d_in, const int* in_sizes, int n_in,
                              void* d_out, int out_size)
{
    const float* src    = (const float*)d_in[0];
    const float* refpts = (const float*)d_in[1];
    // d_in[2] spatial_shapes (int64), d_in[3] level_start_index (int64): compile-time constants
    const float* w_value = (const float*)d_in[4];
    const float* b_value = (const float*)d_in[5];
    const float* w_off   = (const float*)d_in[6];
    const float* b_off   = (const float*)d_in[7];
    const float* w_attn  = (const float*)d_in[8];
    const float* b_attn  = (const float*)d_in[9];
    const float* w_out   = (const float*)d_in[10];
    const float* b_out   = (const float*)d_in[11];
    const float* gamma   = (const float*)d_in[12];
    const float* beta    = (const float*)d_in[13];
    float* out = (float*)d_out;

    float *gv, *go, *ga, *gao, *g2;
    cudaGetSymbolAddress((void**)&gv,  g_value);
    cudaGetSymbolAddress((void**)&go,  g_off);
    cudaGetSymbolAddress((void**)&ga,  g_attn);
    cudaGetSymbolAddress((void**)&gao, g_attout);
    cudaGetSymbolAddress((void**)&g2,  g_out2);

    const int M = MROWS, K = DIM;
    dim3 blk(256);

    // value / offsets / attn projections
    {
        dim3 grid(256 / BN, (M + BM - 1) / BM);
        gemm_bias_kernel<<<grid, blk>>>(src, w_value, b_value, gv, M, 256, K);
        gemm_bias_kernel<<<grid, blk>>>(src, w_off, b_off, go, M, 256, K);
    }
    {
        dim3 grid(128 / BN, (M + BM - 1) / BM);
        gemm_bias_kernel<<<grid, blk>>>(src, w_attn, b_attn, ga, M, 128, K);
    }

    // deformable bilinear sampling + attention-weighted sum
    sample_kernel<<<MROWS, blk>>>(gv, go, ga, refpts, gao);

    // output projection
    {
        dim3 grid(256 / BN, (M + BM - 1) / BM);
        gemm_bias_kernel<<<grid, blk>>>(gao, w_out, b_out, g2, M, 256, K);
    }

    // residual + layernorm
    ln_kernel<<<MROWS, blk>>>(src, g2, gamma, beta, out);
}

// round 2
// speedup vs baseline: 1.0064x; 1.0064x over previous
#include <cuda_runtime.h>
#include <math.h>

#define NB      2
#define LQ      12240
#define DIM     256
#define HEADS   8
#define LEVELS  4
#define POINTS  4
#define HD      32
#define MROWS   (NB * LQ)   // 24480

// Scratch (allocation-free requirement -> __device__ globals)
__device__ float g_value  [MROWS * DIM];
__device__ float g_off    [MROWS * DIM];
__device__ float g_attn   [MROWS * HEADS * 16];
__device__ float g_attout [MROWS * DIM];
__device__ float g_out2   [MROWS * DIM];

typedef unsigned long long u64;

__device__ __forceinline__ u64 ffma2(u64 a, u64 b, u64 c) {
    u64 d;
    asm("fma.rn.f32x2 %0, %1, %2, %3;" : "=l"(d) : "l"(a), "l"(b), "l"(c));
    return d;
}

// ---------------------------------------------------------------------------
// GEMM: C[M,N] = A[M,K] * B[K,N] + bias[N], fp32, packed f32x2 FMA
// BM=128, BN=128, BK=16, 256 threads, 8x8 micro-tile (as 8 rows x 4 f32x2 pairs)
// A smem tile stored DUPLICATED: As2[k][2r]=As2[k][2r+1]=A[r][k], so LDS.128
// yields ready (a,a) f32x2 operands with zero pack movs.
// ---------------------------------------------------------------------------
#define BM 128
#define BN 128
#define BK 16
#define AS_STRIDE (2*BM + 4)   // 260 floats, 1040B: 16B-aligned rows
#define BS_STRIDE (BN + 4)     // 132 floats,  528B: 16B-aligned rows

__global__ __launch_bounds__(256, 2) void gemm_bias_kernel(
    const float* __restrict__ A, const float* __restrict__ B,
    const float* __restrict__ bias, float* __restrict__ C,
    int M, int N, int K)
{
    __shared__ float As2[BK][AS_STRIDE];
    __shared__ float Bs [BK][BS_STRIDE];

    const int tid = threadIdx.x;
    const int tx = tid & 15;          // 0..15 (N dir)
    const int ty = tid >> 4;          // 0..15 (M dir)
    const int bm = blockIdx.y * BM;
    const int bn = blockIdx.x * BN;

    // A load: thread -> one row, 8 consecutive cols (2 float4)
    const int a_row = tid >> 1;              // 0..127
    const int a_col = (tid & 1) * 8;         // 0 or 8
    // B load: thread -> 2 rows (r, r+8), one float4 each
    const int b_row = tid >> 5;              // 0..7
    const int b_col = (tid & 31) * 4;        // 0..124

    u64 acc[8][4];
#pragma unroll
    for (int i = 0; i < 8; i++)
#pragma unroll
        for (int j = 0; j < 4; j++) acc[i][j] = 0ull;

    const bool a_valid = (bm + a_row) < M;

    for (int kk = 0; kk < K; kk += BK) {
        float4 va0 = make_float4(0.f,0.f,0.f,0.f), va1 = va0;
        if (a_valid) {
            const float* ap = &A[(size_t)(bm + a_row) * K + kk + a_col];
            va0 = *(const float4*)(ap);
            va1 = *(const float4*)(ap + 4);
        }
        {
            float av[8] = {va0.x, va0.y, va0.z, va0.w, va1.x, va1.y, va1.z, va1.w};
#pragma unroll
            for (int j = 0; j < 8; j++) {
                float2 d = make_float2(av[j], av[j]);
                *(float2*)&As2[a_col + j][2 * a_row] = d;   // duplicated pair
            }
        }
        {
            float4 vb0 = *(const float4*)&B[(size_t)(kk + b_row) * N + bn + b_col];
            float4 vb1 = *(const float4*)&B[(size_t)(kk + b_row + 8) * N + bn + b_col];
            *(float4*)&Bs[b_row][b_col]     = vb0;
            *(float4*)&Bs[b_row + 8][b_col] = vb1;
        }
        __syncthreads();

#pragma unroll
        for (int k = 0; k < BK; k++) {
            // 8 duplicated A pairs for rows ty*8..ty*8+7 : 4 x LDS.128
            ulonglong2 a01 = *(const ulonglong2*)&As2[k][ty * 16 + 0];
            ulonglong2 a23 = *(const ulonglong2*)&As2[k][ty * 16 + 4];
            ulonglong2 a45 = *(const ulonglong2*)&As2[k][ty * 16 + 8];
            ulonglong2 a67 = *(const ulonglong2*)&As2[k][ty * 16 + 12];
            // 4 B pairs for cols tx*8..tx*8+7 : 2 x LDS.128
            ulonglong2 b01 = *(const ulonglong2*)&Bs[k][tx * 8];
            ulonglong2 b23 = *(const ulonglong2*)&Bs[k][tx * 8 + 4];
            u64 ar[8] = {a01.x, a01.y, a23.x, a23.y, a45.x, a45.y, a67.x, a67.y};
            u64 br[4] = {b01.x, b01.y, b23.x, b23.y};
#pragma unroll
            for (int i = 0; i < 8; i++)
#pragma unroll
                for (int j = 0; j < 4; j++)
                    acc[i][j] = ffma2(ar[i], br[j], acc[i][j]);
        }
        __syncthreads();
    }

    float4 bv0 = *(const float4*)&bias[bn + tx * 8];
    float4 bv1 = *(const float4*)&bias[bn + tx * 8 + 4];
#pragma unroll
    for (int i = 0; i < 8; i++) {
        int row = bm + ty * 8 + i;
        if (row < M) {
            float2 p0 = *(float2*)&acc[i][0];
            float2 p1 = *(float2*)&acc[i][1];
            float2 p2 = *(float2*)&acc[i][2];
            float2 p3 = *(float2*)&acc[i][3];
            float4 o0 = make_float4(p0.x + bv0.x, p0.y + bv0.y, p1.x + bv0.z, p1.y + bv0.w);
            float4 o1 = make_float4(p2.x + bv1.x, p2.y + bv1.y, p3.x + bv1.z, p3.y + bv1.w);
            float* cp = &C[(size_t)row * N + bn + tx * 8];
            *(float4*)(cp)     = o0;
            *(float4*)(cp + 4) = o1;
        }
    }
}

// ---------------------------------------------------------------------------
// Deformable sampling: warp == (query, head); lane p(=lane&15) preps point p,
// gather phase broadcasts via shfl. Validity folded into weights (zeroed),
// indices clamped -> unconditional loads.
// ---------------------------------------------------------------------------
__global__ __launch_bounds__(256) void sample_kernel(
    const float* __restrict__ value,
    const float* __restrict__ off,
    const float* __restrict__ logits,
    const float* __restrict__ ref,
    float* __restrict__ out)
{
    const unsigned FULL = 0xffffffffu;
    const int qg   = blockIdx.x;            // 0..MROWS-1
    const int n    = qg / LQ;
    const int h    = threadIdx.x >> 5;
    const int lane = threadIdx.x & 31;
    const int p    = lane & 15;              // point id (dup in upper half-warp)
    const int l    = p >> 2;                 // level

    // --- softmax over 16 logits (each lane owns one; xor-reduce within 16) ---
    float lg = logits[(size_t)qg * (HEADS * 16) + h * 16 + p];
    float mx = lg;
#pragma unroll
    for (int o = 8; o > 0; o >>= 1)
        mx = fmaxf(mx, __shfl_xor_sync(FULL, mx, o));
    float e = __expf(lg - mx);
    float sum = e;
#pragma unroll
    for (int o = 8; o > 0; o >>= 1)
        sum += __shfl_xor_sync(FULL, sum, o);
    const float aw = __fdividef(e, sum);

    // --- per-point bilinear prep (lane p) ---
    const int W  = 96 >> l;                        // H == W per level
    const int S0 = 12288 - 3 * (4096 >> (2 * l));  // level start row
    const float rx = ref[(size_t)qg * (LEVELS * 2) + l * 2 + 0] * (float)W;
    const float ry = ref[(size_t)qg * (LEVELS * 2) + l * 2 + 1] * (float)W;
    const float ox = off[(size_t)qg * DIM + h * 32 + p * 2 + 0];
    const float oy = off[(size_t)qg * DIM + h * 32 + p * 2 + 1];
    const float x = rx + ox - 0.5f;
    const float y = ry + oy - 0.5f;
    const float x0f = floorf(x), y0f = floorf(y);
    const int x0 = (int)x0f, y0 = (int)y0f;
    const float fx = x - x0f, fy = y - y0f;

    const float vx0 = (x0 >= 0 && x0 < W) ? 1.f : 0.f;
    const float vx1 = (x0 + 1 >= 0 && x0 + 1 < W) ? 1.f : 0.f;
    const float vy0 = (y0 >= 0 && y0 < W) ? 1.f : 0.f;
    const float vy1 = (y0 + 1 >= 0 && y0 + 1 < W) ? 1.f : 0.f;
    const float wx0 = (1.f - fx) * vx0;
    const float wx1 = fx * vx1;
    const float wy0 = (1.f - fy) * aw * vy0;
    const float wy1 = fy * aw * vy1;
    float w00 = wx0 * wy0, w01 = wx1 * wy0, w10 = wx0 * wy1, w11 = wx1 * wy1;
    int c0 = min(max(x0, 0), W - 1) * DIM;
    int c1 = min(max(x0 + 1, 0), W - 1) * DIM;
    int r0 = (S0 + min(max(y0, 0), W - 1) * W) * DIM;
    int r1 = (S0 + min(max(y0 + 1, 0), W - 1) * W) * DIM;

    // --- gather: lane == channel ---
    const float* vb = value + (size_t)n * (LQ * DIM) + h * HD + lane;
    float acc = 0.f;
#pragma unroll
    for (int q = 0; q < 16; q++) {
        const float u00 = __shfl_sync(FULL, w00, q);
        const float u01 = __shfl_sync(FULL, w01, q);
        const float u10 = __shfl_sync(FULL, w10, q);
        const float u11 = __shfl_sync(FULL, w11, q);
        const int a0 = __shfl_sync(FULL, r0, q);
        const int a1 = __shfl_sync(FULL, r1, q);
        const int b0 = __shfl_sync(FULL, c0, q);
        const int b1 = __shfl_sync(FULL, c1, q);
        acc = fmaf(u00, vb[a0 + b0], acc);
        acc = fmaf(u01, vb[a0 + b1], acc);
        acc = fmaf(u10, vb[a1 + b0], acc);
        acc = fmaf(u11, vb[a1 + b1], acc);
    }
    out[(size_t)qg * DIM + h * HD + lane] = acc;
}

// ---------------------------------------------------------------------------
// Residual + LayerNorm: 1 block per row (256 threads == DIM)
// ---------------------------------------------------------------------------
__global__ __launch_bounds__(256) void ln_kernel(
    const float* __restrict__ src, const float* __restrict__ y,
    const float* __restrict__ gamma, const float* __restrict__ beta,
    float* __restrict__ out)
{
    const int row = blockIdx.x;
    const int t = threadIdx.x;
    const size_t idx = (size_t)row * DIM + t;
    const float x = src[idx] + y[idx];

    float s = x, s2 = x * x;
#pragma unroll
    for (int o = 16; o > 0; o >>= 1) {
        s  += __shfl_down_sync(0xffffffffu, s, o);
        s2 += __shfl_down_sync(0xffffffffu, s2, o);
    }
    __shared__ float ss[8], ss2[8];
    const int w = t >> 5;
    if ((t & 31) == 0) { ss[w] = s; ss2[w] = s2; }
    __syncthreads();
    float sum = 0.f, sum2 = 0.f;
#pragma unroll
    for (int i = 0; i < 8; i++) { sum += ss[i]; sum2 += ss2[i]; }

    const float mu  = sum * (1.0f / DIM);
    const float var = sum2 * (1.0f / DIM) - mu * mu;
    const float r = rsqrtf(var + 1e-5f);
    out[idx] = (x - mu) * r * gamma[t] + beta[t];
}

// ---------------------------------------------------------------------------
extern "C" void kernel_launch(void* const* d_in, const int* in_sizes, int n_in,
                              void* d_out, int out_size)
{
    const float* src    = (const float*)d_in[0];
    const float* refpts = (const float*)d_in[1];
    const float* w_value = (const float*)d_in[4];
    const float* b_value = (const float*)d_in[5];
    const float* w_off   = (const float*)d_in[6];
    const float* b_off   = (const float*)d_in[7];
    const float* w_attn  = (const float*)d_in[8];
    const float* b_attn  = (const float*)d_in[9];
    const float* w_out   = (const float*)d_in[10];
    const float* b_out   = (const float*)d_in[11];
    const float* gamma   = (const float*)d_in[12];
    const float* beta    = (const float*)d_in[13];
    float* out = (float*)d_out;

    float *gv, *go, *ga, *gao, *g2;
    cudaGetSymbolAddress((void**)&gv,  g_value);
    cudaGetSymbolAddress((void**)&go,  g_off);
    cudaGetSymbolAddress((void**)&ga,  g_attn);
    cudaGetSymbolAddress((void**)&gao, g_attout);
    cudaGetSymbolAddress((void**)&g2,  g_out2);

    const int M = MROWS, K = DIM;
    dim3 blk(256);
    const int gy = (M + BM - 1) / BM;   // 192

    gemm_bias_kernel<<<dim3(256 / BN, gy), blk>>>(src, w_value, b_value, gv, M, 256, K);
    gemm_bias_kernel<<<dim3(256 / BN, gy), blk>>>(src, w_off,   b_off,   go, M, 256, K);
    gemm_bias_kernel<<<dim3(128 / BN, gy), blk>>>(src, w_attn,  b_attn,  ga, M, 128, K);

    sample_kernel<<<MROWS, blk>>>(gv, go, ga, refpts, gao);

    gemm_bias_kernel<<<dim3(256 / BN, gy), blk>>>(gao, w_out, b_out, g2, M, 256, K);

    ln_kernel<<<MROWS, blk>>>(src, g2, gamma, beta, out);
}